// round 10
// baseline (speedup 1.0000x reference)
#include <cuda_runtime.h>
#include <cuda_bf16.h>
#include <math_constants.h>
#include <cstdint>

// Problem constants
#define BQ 1024
#define DD 512
#define NN 131072
#define KK 16
#define NCAND 48
#define NTILES (NN / 128)       // 1024 n-tiles
#define PPT 8                   // partial entries per (query, tile)

#define QSCALE 396.875f         // 127 / 0.32

// ---------------------------------------------------------------------------
// Helpers
// ---------------------------------------------------------------------------
__device__ __forceinline__ uint32_t smem_u32(const void* p) {
    uint32_t a;
    asm("{ .reg .u64 t; cvta.to.shared.u64 t, %1; cvt.u32.u64 %0, t; }" : "=r"(a) : "l"(p));
    return a;
}
// swizzle for 64B-pitch s8 tiles: XOR 16B-chunk bits with row bits [1:3)
__device__ __forceinline__ uint32_t sw64(uint32_t o) { return o ^ (((o >> 7) & 3u) << 4); }

__device__ __forceinline__ int8_t q8(float x) {
    int v = __float2int_rn(x * QSCALE);
    v = v < -127 ? -127 : (v > 127 ? 127 : v);
    return (int8_t)v;
}
__device__ __forceinline__ unsigned short s32_key(int c) {
    int k = c >> 3;
    k = k < -32768 ? -32768 : (k > 32767 ? 32767 : k);
    return (unsigned short)(k + 32768);
}

#define CP_ASYNC16(smem_addr, gptr) \
    asm volatile("cp.async.cg.shared.global [%0], [%1], 16;" :: "r"(smem_addr), "l"(gptr))
#define CP_COMMIT() asm volatile("cp.async.commit_group;")
#define CP_WAIT(N)  asm volatile("cp.async.wait_group %0;" :: "n"(N))

#define LDMATRIX_X4(r0, r1, r2, r3, addr) \
    asm volatile("ldmatrix.sync.aligned.m8n8.x4.shared.b16 {%0,%1,%2,%3}, [%4];" \
        : "=r"(r0), "=r"(r1), "=r"(r2), "=r"(r3) : "r"(addr))

#define MMA_S8(c, a, b) \
    asm volatile("mma.sync.aligned.m16n8k32.row.col.s32.s8.s8.s32 " \
        "{%0,%1,%2,%3}, {%4,%5,%6,%7}, {%8,%9}, {%0,%1,%2,%3};" \
        : "+r"((c)[0]), "+r"((c)[1]), "+r"((c)[2]), "+r"((c)[3]) \
        : "r"((a)[0]), "r"((a)[1]), "r"((a)[2]), "r"((a)[3]), "r"((b)[0]), "r"((b)[1]))

// ---------------------------------------------------------------------------
// Scratch
// ---------------------------------------------------------------------------
__device__ float          g_qn[BQ * DD];
__device__ int8_t         g_q8[BQ * DD];
__device__ float          g_wt[(size_t)NN * DD];
__device__ int8_t         g_w8[(size_t)NN * DD];
__device__ unsigned short g_pk[(size_t)BQ * NTILES * PPT];   // packed keys, 16MB
__device__ unsigned char  g_pl[(size_t)BQ * NTILES * PPT];   // local cols,   8MB
__device__ int            g_cand[BQ * NCAND];

// ---------------------------------------------------------------------------
// Kernel 1: normalize queries -> fp32 + int8
// ---------------------------------------------------------------------------
__global__ __launch_bounds__(128) void normalize_kernel(const float* __restrict__ q) {
    int row = blockIdx.x;
    const float* src = q + (size_t)row * DD;
    float v[4];
    float s = 0.f;
#pragma unroll
    for (int i = 0; i < 4; i++) { v[i] = src[threadIdx.x + i * 128]; s += v[i] * v[i]; }
#pragma unroll
    for (int o = 16; o > 0; o >>= 1) s += __shfl_xor_sync(0xffffffffu, s, o);
    __shared__ float red[4];
    if ((threadIdx.x & 31) == 0) red[threadIdx.x >> 5] = s;
    __syncthreads();
    float inv = rsqrtf(red[0] + red[1] + red[2] + red[3]);
#pragma unroll
    for (int i = 0; i < 4; i++) {
        float f = v[i] * inv;
        int d = threadIdx.x + i * 128;
        g_qn[(size_t)row * DD + d] = f;
        g_q8[(size_t)row * DD + d] = q8(f);
    }
}

// ---------------------------------------------------------------------------
// Kernel 2: transpose W[D,N] -> W_t[N,D] fp32 + int8
// ---------------------------------------------------------------------------
#define TP 65   // smem pitch (floats)

__global__ __launch_bounds__(256) void transpose_kernel(const float* __restrict__ W) {
    __shared__ float tile[64 * TP];
    const int bx = blockIdx.x;
    const int by = blockIdx.y;
    const int t  = threadIdx.x;

    {
        const int r = t >> 2, s = t & 3;
        const float* src = W + (size_t)(by * 64 + r) * NN + bx * 64 + s * 16;
#pragma unroll
        for (int j = 0; j < 4; j++) {
            float4 v = *(const float4*)(src + j * 4);
            float* dst = &tile[r * TP + s * 16 + j * 4];
            dst[0] = v.x; dst[1] = v.y; dst[2] = v.z; dst[3] = v.w;
        }
    }
    __syncthreads();

    {
        const int nr = t >> 2, s = t & 3;
        const int n = bx * 64 + nr;
        const int d0 = by * 64 + s * 16;
        float vals[16];
#pragma unroll
        for (int j = 0; j < 16; j++)
            vals[j] = tile[(s * 16 + j) * TP + nr];

        float* dst32 = g_wt + (size_t)n * DD + d0;
#pragma unroll
        for (int j = 0; j < 4; j++)
            *(float4*)(dst32 + j * 4) = make_float4(vals[4*j], vals[4*j+1], vals[4*j+2], vals[4*j+3]);

        uint32_t pk[4];
#pragma unroll
        for (int j = 0; j < 4; j++) {
            uint32_t b0 = (uint8_t)q8(vals[4*j + 0]);
            uint32_t b1 = (uint8_t)q8(vals[4*j + 1]);
            uint32_t b2 = (uint8_t)q8(vals[4*j + 2]);
            uint32_t b3 = (uint8_t)q8(vals[4*j + 3]);
            pk[j] = b0 | (b1 << 8) | (b2 << 16) | (b3 << 24);
        }
        *(uint4*)(g_w8 + (size_t)n * DD + d0) = make_uint4(pk[0], pk[1], pk[2], pk[3]);
    }
}

// ---------------------------------------------------------------------------
// Kernel 3: int8 MMA GEMM + fused top-4 per (row, half-tile); packed output.
// CTA tile 128x128, K chunk = 64 bytes, 8 warps (2m x 4n), 3-stage cp.async.
// ---------------------------------------------------------------------------
#define STG_BYTES 16384         // A 8KB + B 8KB per stage
#define SMEM_TOTAL 49152

__global__ __launch_bounds__(256, 2) void gemm_kernel() {
    extern __shared__ char smem[];
    const uint32_t sb = smem_u32(smem);
    const int tid = threadIdx.x, wid = tid >> 5, lane = tid & 31;
    const int q0 = blockIdx.x * 128;
    const int nb = blockIdx.y * 128;

    auto issue = [&](int kc, int stg) {
        const int8_t* As = g_q8 + (size_t)q0 * DD + kc * 64;
        const int8_t* Bs = g_w8 + (size_t)nb * DD + kc * 64;
#pragma unroll
        for (int i = 0; i < 2; i++) {
            int flat = tid + i * 256;          // 0..511
            int row = flat >> 2, seg = flat & 3;
            uint32_t off = sw64((uint32_t)(row * 64 + seg * 16));
            CP_ASYNC16(sb + stg * STG_BYTES + off,        As + (size_t)row * DD + seg * 16);
            CP_ASYNC16(sb + stg * STG_BYTES + 8192 + off, Bs + (size_t)row * DD + seg * 16);
        }
        CP_COMMIT();
    };

    int c[4][4][4];
#pragma unroll
    for (int mi = 0; mi < 4; mi++)
#pragma unroll
        for (int ni = 0; ni < 4; ni++)
#pragma unroll
            for (int r = 0; r < 4; r++) c[mi][ni][r] = 0;

    const int wm = (wid >> 2) * 64;
    const int wn = (wid & 3) * 32;
    const int lrow = lane & 15;
    const int lkh  = lane >> 4;

    issue(0, 0);
    issue(1, 1);

#pragma unroll 1
    for (int kc = 0; kc < 8; kc++) {
        const int stg = kc % 3;
        if (kc == 7) { CP_WAIT(0); } else { CP_WAIT(1); }
        __syncthreads();
        if (kc + 2 < 8) issue(kc + 2, (kc + 2) % 3);

        const uint32_t ab = sb + stg * STG_BYTES;
        const uint32_t bb = ab + 8192;
#pragma unroll
        for (int ks = 0; ks < 2; ks++) {
            uint32_t a[4][4];
#pragma unroll
            for (int mi = 0; mi < 4; mi++) {
                uint32_t addr = ab + sw64((uint32_t)((wm + mi * 16 + lrow) * 64 + ks * 32 + lkh * 16));
                LDMATRIX_X4(a[mi][0], a[mi][1], a[mi][2], a[mi][3], addr);
            }
            uint32_t b[4][2];
#pragma unroll
            for (int nj = 0; nj < 2; nj++) {
                uint32_t r0, r1, r2, r3;
                uint32_t addr = bb + sw64((uint32_t)((wn + nj * 16 + lrow) * 64 + ks * 32 + lkh * 16));
                LDMATRIX_X4(r0, r1, r2, r3, addr);
                b[2 * nj][0] = r0; b[2 * nj + 1][0] = r1;
                b[2 * nj][1] = r2; b[2 * nj + 1][1] = r3;
            }
#pragma unroll
            for (int mi = 0; mi < 4; mi++)
#pragma unroll
                for (int ni = 0; ni < 4; ni++)
                    MMA_S8(c[mi][ni], a[mi], b[ni]);
        }
    }
    __syncthreads();   // all MMAs done before key-staging reuses stage SMEM

    // ---- stage C tile as u16 keys (128 rows x 256B) ----
    const int crow = lane >> 2;
    const int ccol2 = (lane & 3) * 2;
#pragma unroll
    for (int mi = 0; mi < 4; mi++)
#pragma unroll
        for (int ni = 0; ni < 4; ni++) {
            int m = wm + mi * 16 + crow;
            int n = wn + ni * 8 + ccol2;
            ushort2 lo, hi;
            lo.x = s32_key(c[mi][ni][0]); lo.y = s32_key(c[mi][ni][1]);
            hi.x = s32_key(c[mi][ni][2]); hi.y = s32_key(c[mi][ni][3]);
            *(ushort2*)(smem + m * 256 + n * 2)       = lo;
            *(ushort2*)(smem + (m + 8) * 256 + n * 2) = hi;
        }
    __syncthreads();

    // ---- fused selection: 2 threads per query row, 64 cols each, top-4 ----
    {
        const int row  = tid >> 1;
        const int half = tid & 1;
        int v0 = -1, v1 = -1, v2 = -1, v3 = -1;
        int i0 = 0, i1 = 0, i2 = 0, i3 = 0;
        const int rot = 2 * (row & 15) + half;
#pragma unroll
        for (int p = 0; p < 32; p++) {
            int pp = (p + rot) & 31;
            uint32_t w = *(uint32_t*)(smem + row * 256 + half * 128 + pp * 4);
            int n0 = half * 64 + pp * 2;
#pragma unroll
            for (int h = 0; h < 2; h++) {
                int x = h ? (int)(w >> 16) : (int)(w & 0xFFFFu);
                int n = n0 + h;
                bool p0c = x > v0, p1c = x > v1, p2c = x > v2, p3c = x > v3;
                v3 = p2c ? v2 : (p3c ? x : v3);  i3 = p2c ? i2 : (p3c ? n : i3);
                v2 = p1c ? v1 : (p2c ? x : v2);  i2 = p1c ? i1 : (p2c ? n : i2);
                v1 = p0c ? v0 : (p1c ? x : v1);  i1 = p0c ? i0 : (p1c ? n : i1);
                v0 = p0c ? x  : v0;              i0 = p0c ? n : i0;
            }
        }
        size_t base = ((size_t)(q0 + row) * NTILES + blockIdx.y) * PPT + half * 4;
        ushort4 ks;
        ks.x = (unsigned short)v0; ks.y = (unsigned short)v1;
        ks.z = (unsigned short)v2; ks.w = (unsigned short)v3;
        *(ushort4*)(g_pk + base) = ks;
        *(uchar4*)(g_pl + base) = make_uchar4((unsigned char)i0, (unsigned char)i1,
                                              (unsigned char)i2, (unsigned char)i3);
    }
}

// ---------------------------------------------------------------------------
// Kernel 4: per-query top-48 from packed partials
// ---------------------------------------------------------------------------
#define TL 8
__global__ __launch_bounds__(256) void cand_kernel() {
    const int q = blockIdx.x;
    const int tid = threadIdx.x;
    const unsigned short* pk = g_pk + (size_t)q * NTILES * PPT;
    const unsigned char*  pl = g_pl + (size_t)q * NTILES * PPT;

    int tv[TL]; int ti[TL];
#pragma unroll
    for (int i = 0; i < TL; i++) { tv[i] = -1; ti[i] = 0x7fffffff; }

#pragma unroll
    for (int b = 0; b < 4; b++) {
        const int tile = tid * 4 + b;
        uint4 kv = *(const uint4*)(pk + tile * 8);
        uint2 lv = *(const uint2*)(pl + tile * 8);
        uint32_t kw[4] = {kv.x, kv.y, kv.z, kv.w};
        uint32_t lw[2] = {lv.x, lv.y};
#pragma unroll
        for (int e = 0; e < 8; e++) {
            int kk = (int)((kw[e >> 1] >> ((e & 1) * 16)) & 0xFFFFu);
            int gg = tile * 128 + (int)((lw[e >> 2] >> ((e & 3) * 8)) & 0xFFu);
            bool c0 = (kk > tv[0]) || (kk == tv[0] && gg < ti[0]);
            bool c1 = (kk > tv[1]) || (kk == tv[1] && gg < ti[1]);
            bool c2 = (kk > tv[2]) || (kk == tv[2] && gg < ti[2]);
            bool c3 = (kk > tv[3]) || (kk == tv[3] && gg < ti[3]);
            bool c4 = (kk > tv[4]) || (kk == tv[4] && gg < ti[4]);
            bool c5 = (kk > tv[5]) || (kk == tv[5] && gg < ti[5]);
            bool c6 = (kk > tv[6]) || (kk == tv[6] && gg < ti[6]);
            bool c7 = (kk > tv[7]) || (kk == tv[7] && gg < ti[7]);
            tv[7] = c6 ? tv[6] : (c7 ? kk : tv[7]);  ti[7] = c6 ? ti[6] : (c7 ? gg : ti[7]);
            tv[6] = c5 ? tv[5] : (c6 ? kk : tv[6]);  ti[6] = c5 ? ti[5] : (c6 ? gg : ti[6]);
            tv[5] = c4 ? tv[4] : (c5 ? kk : tv[5]);  ti[5] = c4 ? ti[4] : (c5 ? gg : ti[5]);
            tv[4] = c3 ? tv[3] : (c4 ? kk : tv[4]);  ti[4] = c3 ? ti[3] : (c4 ? gg : ti[4]);
            tv[3] = c2 ? tv[2] : (c3 ? kk : tv[3]);  ti[3] = c2 ? ti[2] : (c3 ? gg : ti[3]);
            tv[2] = c1 ? tv[1] : (c2 ? kk : tv[2]);  ti[2] = c1 ? ti[1] : (c2 ? gg : ti[2]);
            tv[1] = c0 ? tv[0] : (c1 ? kk : tv[1]);  ti[1] = c0 ? ti[0] : (c1 ? gg : ti[1]);
            tv[0] = c0 ? kk : tv[0];                 ti[0] = c0 ? gg : ti[0];
        }
    }

    __shared__ int sv[256 * TL];
    __shared__ int si[256 * TL];
#pragma unroll
    for (int i = 0; i < TL; i++) {
        sv[tid * TL + i] = tv[i];
        si[tid * TL + i] = ti[i];
    }
    __syncthreads();

    if (tid < 32) {
        const int l = tid;
        int hv[8]; int hx[8]; int hp[8];
#pragma unroll
        for (int s = 0; s < 8; s++) {
            int t = l * 8 + s;
            hv[s] = sv[t * TL]; hx[s] = si[t * TL]; hp[s] = 0;
        }
#pragma unroll 1
        for (int sel = 0; sel < NCAND; sel++) {
            int bv = -1; int bi = 0x7fffffff; int bs = 0;
#pragma unroll
            for (int s = 0; s < 8; s++)
                if (hv[s] > bv || (hv[s] == bv && hx[s] < bi)) { bv = hv[s]; bi = hx[s]; bs = s; }
            int wv = bv; int wi = bi; int wl = l;
#pragma unroll
            for (int off = 16; off > 0; off >>= 1) {
                int ov = __shfl_xor_sync(0xffffffffu, wv, off);
                int oi = __shfl_xor_sync(0xffffffffu, wi, off);
                int ol = __shfl_xor_sync(0xffffffffu, wl, off);
                if (ov > wv || (ov == wv && oi < wi)) { wv = ov; wi = oi; wl = ol; }
            }
            if (l == wl) {
                g_cand[q * NCAND + sel] = wi;
                int t = l * 8 + bs;
                hp[bs]++;
                if (hp[bs] < TL) { hv[bs] = sv[t * TL + hp[bs]]; hx[bs] = si[t * TL + hp[bs]]; }
                else             { hv[bs] = -1;                 hx[bs] = 0x7fffffff; }
            }
        }
    }
}

// ---------------------------------------------------------------------------
// Kernel 5: sequential-fp32 rescore of 48 candidates, top-16, write outputs
// ---------------------------------------------------------------------------
#define CHUNK 128
#define CPITCH 129

__global__ __launch_bounds__(256) void refine_kernel(const float* __restrict__ label,
                                                     float* __restrict__ out_scores,
                                                     float* __restrict__ out_idx_f,
                                                     float* __restrict__ out_seqs,
                                                     float* __restrict__ out_labels) {
    const int q = blockIdx.x;
    const int tid = threadIdx.x;

    __shared__ float qn_s[DD];
    __shared__ float chunk[NCAND * CPITCH];
    __shared__ float cv[NCAND];
    __shared__ int   ci[NCAND];
    __shared__ int   sel_idx[KK];

    if (tid < NCAND) ci[tid] = g_cand[q * NCAND + tid];
    for (int d = tid; d < DD; d += 256) qn_s[d] = g_qn[(size_t)q * DD + d];
    __syncthreads();

    float acc = 0.f;
#pragma unroll 1
    for (int ch = 0; ch < DD / CHUNK; ch++) {
        for (int idx = tid; idx < NCAND * CHUNK; idx += 256) {
            int c = idx >> 7, d = idx & (CHUNK - 1);
            chunk[c * CPITCH + d] = g_wt[(size_t)ci[c] * DD + ch * CHUNK + d];
        }
        __syncthreads();
        if (tid < NCAND) {
#pragma unroll
            for (int d = 0; d < CHUNK; d++)
                acc = fmaf(chunk[tid * CPITCH + d], qn_s[ch * CHUNK + d], acc);
        }
        __syncthreads();
    }
    if (tid < NCAND) cv[tid] = acc;
    __syncthreads();

    if (tid == 0) {
        bool used[NCAND] = {};
        for (int r = 0; r < KK; r++) {
            float best = -CUDART_INF_F; int bj = -1; int bidx = 0x7fffffff;
            for (int j = 0; j < NCAND; j++) {
                if (used[j]) continue;
                if (cv[j] > best || (cv[j] == best && ci[j] < bidx)) {
                    best = cv[j]; bj = j; bidx = ci[j];
                }
            }
            used[bj] = true;
            sel_idx[r] = ci[bj];
            out_scores[q * KK + r] = best;
            out_idx_f [q * KK + r] = (float)ci[bj];
            out_labels[q * KK + r] = label[ci[bj]];
        }
    }
    __syncthreads();

#pragma unroll 1
    for (int r = 0; r < KK; r++) {
        const float* row = g_wt + (size_t)sel_idx[r] * DD;
        float* dst = out_seqs + ((size_t)q * KK + r) * DD;
        for (int d = tid; d < DD; d += 256) dst[d] = row[d];
    }
}

// ---------------------------------------------------------------------------
// Launcher
// ---------------------------------------------------------------------------
extern "C" void kernel_launch(void* const* d_in, const int* in_sizes, int n_in,
                              void* d_out, int out_size) {
    const float* queries = (const float*)d_in[0];
    const float* weight  = (const float*)d_in[1];
    const float* label   = (const float*)d_in[2];

    float* out = (float*)d_out;
    float* out_scores = out;
    float* out_idx_f  = out + BQ * KK;
    float* out_seqs   = out + 2 * BQ * KK;
    float* out_labels = out + 2 * BQ * KK + (size_t)BQ * KK * DD;

    cudaFuncSetAttribute(gemm_kernel, cudaFuncAttributeMaxDynamicSharedMemorySize, SMEM_TOTAL);

    normalize_kernel<<<BQ, 128>>>(queries);
    transpose_kernel<<<dim3(NN / 64, DD / 64), 256>>>(weight);
    gemm_kernel<<<dim3(BQ / 128, NN / 128), 256, SMEM_TOTAL>>>();
    cand_kernel<<<BQ, 256>>>();
    refine_kernel<<<BQ, 256>>>(label, out_scores, out_idx_f, out_seqs, out_labels);
}

// round 11
// speedup vs baseline: 1.0747x; 1.0747x over previous
#include <cuda_runtime.h>
#include <cuda_bf16.h>
#include <math_constants.h>
#include <cstdint>

// Problem constants
#define BQ 1024
#define DD 512
#define NN 131072
#define KK 16
#define NCAND 48
#define NTILES (NN / 128)       // 1024 n-tiles
#define PPT 8                   // partial entries per (query, tile)

#define QSCALE 396.875f         // 127 / 0.32

// ---------------------------------------------------------------------------
// Helpers
// ---------------------------------------------------------------------------
__device__ __forceinline__ uint32_t smem_u32(const void* p) {
    uint32_t a;
    asm("{ .reg .u64 t; cvta.to.shared.u64 t, %1; cvt.u32.u64 %0, t; }" : "=r"(a) : "l"(p));
    return a;
}
__device__ __forceinline__ uint32_t sw128(uint32_t o) { return o ^ ((o >> 3) & 0x70); }

__device__ __forceinline__ int8_t q8(float x) {
    int v = __float2int_rn(x * QSCALE);
    v = v < -127 ? -127 : (v > 127 ? 127 : v);
    return (int8_t)v;
}
__device__ __forceinline__ unsigned short s32_key(int c) {
    int k = c >> 3;
    k = k < -32768 ? -32768 : (k > 32767 ? 32767 : k);
    return (unsigned short)(k + 32768);
}

#define CP_ASYNC16(smem_addr, gptr) \
    asm volatile("cp.async.cg.shared.global [%0], [%1], 16;" :: "r"(smem_addr), "l"(gptr))
#define CP_COMMIT() asm volatile("cp.async.commit_group;")
#define CP_WAIT(N)  asm volatile("cp.async.wait_group %0;" :: "n"(N))

#define LDMATRIX_X4(r0, r1, r2, r3, addr) \
    asm volatile("ldmatrix.sync.aligned.m8n8.x4.shared.b16 {%0,%1,%2,%3}, [%4];" \
        : "=r"(r0), "=r"(r1), "=r"(r2), "=r"(r3) : "r"(addr))

#define MMA_S8(c, a, b) \
    asm volatile("mma.sync.aligned.m16n8k32.row.col.s32.s8.s8.s32 " \
        "{%0,%1,%2,%3}, {%4,%5,%6,%7}, {%8,%9}, {%0,%1,%2,%3};" \
        : "+r"((c)[0]), "+r"((c)[1]), "+r"((c)[2]), "+r"((c)[3]) \
        : "r"((a)[0]), "r"((a)[1]), "r"((a)[2]), "r"((a)[3]), "r"((b)[0]), "r"((b)[1]))

// ---------------------------------------------------------------------------
// Scratch
// ---------------------------------------------------------------------------
__device__ float          g_qn[BQ * DD];
__device__ int8_t         g_q8[BQ * DD];
__device__ float          g_wt[(size_t)NN * DD];
__device__ int8_t         g_w8[(size_t)NN * DD];
__device__ unsigned short g_pk[(size_t)BQ * NTILES * PPT];   // packed keys, 16MB
__device__ unsigned char  g_pl[(size_t)BQ * NTILES * PPT];   // local cols,   8MB
__device__ int            g_cand[BQ * NCAND];

// ---------------------------------------------------------------------------
// Kernel 1: normalize queries -> fp32 + int8
// ---------------------------------------------------------------------------
__global__ __launch_bounds__(128) void normalize_kernel(const float* __restrict__ q) {
    int row = blockIdx.x;
    const float* src = q + (size_t)row * DD;
    float v[4];
    float s = 0.f;
#pragma unroll
    for (int i = 0; i < 4; i++) { v[i] = src[threadIdx.x + i * 128]; s += v[i] * v[i]; }
#pragma unroll
    for (int o = 16; o > 0; o >>= 1) s += __shfl_xor_sync(0xffffffffu, s, o);
    __shared__ float red[4];
    if ((threadIdx.x & 31) == 0) red[threadIdx.x >> 5] = s;
    __syncthreads();
    float inv = rsqrtf(red[0] + red[1] + red[2] + red[3]);
#pragma unroll
    for (int i = 0; i < 4; i++) {
        float f = v[i] * inv;
        int d = threadIdx.x + i * 128;
        g_qn[(size_t)row * DD + d] = f;
        g_q8[(size_t)row * DD + d] = q8(f);
    }
}

// ---------------------------------------------------------------------------
// Kernel 2: transpose W[D,N] -> W_t[N,D] fp32 + int8
// ---------------------------------------------------------------------------
#define TP 65   // smem pitch (floats)

__global__ __launch_bounds__(256) void transpose_kernel(const float* __restrict__ W) {
    __shared__ float tile[64 * TP];
    const int bx = blockIdx.x;
    const int by = blockIdx.y;
    const int t  = threadIdx.x;

    {
        const int r = t >> 2, s = t & 3;
        const float* src = W + (size_t)(by * 64 + r) * NN + bx * 64 + s * 16;
#pragma unroll
        for (int j = 0; j < 4; j++) {
            float4 v = *(const float4*)(src + j * 4);
            float* dst = &tile[r * TP + s * 16 + j * 4];
            dst[0] = v.x; dst[1] = v.y; dst[2] = v.z; dst[3] = v.w;
        }
    }
    __syncthreads();

    {
        const int nr = t >> 2, s = t & 3;
        const int n = bx * 64 + nr;
        const int d0 = by * 64 + s * 16;
        float vals[16];
#pragma unroll
        for (int j = 0; j < 16; j++)
            vals[j] = tile[(s * 16 + j) * TP + nr];

        float* dst32 = g_wt + (size_t)n * DD + d0;
#pragma unroll
        for (int j = 0; j < 4; j++)
            *(float4*)(dst32 + j * 4) = make_float4(vals[4*j], vals[4*j+1], vals[4*j+2], vals[4*j+3]);

        uint32_t pk[4];
#pragma unroll
        for (int j = 0; j < 4; j++) {
            uint32_t b0 = (uint8_t)q8(vals[4*j + 0]);
            uint32_t b1 = (uint8_t)q8(vals[4*j + 1]);
            uint32_t b2 = (uint8_t)q8(vals[4*j + 2]);
            uint32_t b3 = (uint8_t)q8(vals[4*j + 3]);
            pk[j] = b0 | (b1 << 8) | (b2 << 16) | (b3 << 24);
        }
        *(uint4*)(g_w8 + (size_t)n * DD + d0) = make_uint4(pk[0], pk[1], pk[2], pk[3]);
    }
}

// ---------------------------------------------------------------------------
// Kernel 3: int8 MMA GEMM + fused top-4 per (row, half-tile); packed output.
// CTA tile 128x128, K chunk = 128 BYTES (128 s8) -> 128B row pitch + sw128,
// the exact conflict-free layout proven by the bf16 kernel. 4 k-chunks.
// 8 warps (2m x 4n), 3-stage cp.async pipeline.
// ---------------------------------------------------------------------------
#define STG_A(s) ((uint32_t)((s) * 16384))
#define STG_B(s) ((uint32_t)(49152 + (s) * 16384))
#define SMEM_TOTAL 98304

__global__ __launch_bounds__(256, 2) void gemm_kernel() {
    extern __shared__ char smem[];
    const uint32_t sb = smem_u32(smem);
    const int tid = threadIdx.x, wid = tid >> 5, lane = tid & 31;
    const int q0 = blockIdx.x * 128;
    const int nb = blockIdx.y * 128;

    const int ldrow = tid >> 3;          // base row 0..31 (x4 -> 128 rows)
    const int ldseg = tid & 7;           // 16B segment within 128B row

    auto issue = [&](int kc, int stg) {
        const int8_t* As = g_q8 + (size_t)q0 * DD + kc * 128;
        const int8_t* Bs = g_w8 + (size_t)nb * DD + kc * 128;
#pragma unroll
        for (int i = 0; i < 4; i++) {
            int row = ldrow + i * 32;
            uint32_t off = sw128((uint32_t)(row * 128 + ldseg * 16));
            CP_ASYNC16(sb + STG_A(stg) + off, As + (size_t)row * DD + ldseg * 16);
            CP_ASYNC16(sb + STG_B(stg) + off, Bs + (size_t)row * DD + ldseg * 16);
        }
        CP_COMMIT();
    };

    int c[4][4][4];
#pragma unroll
    for (int mi = 0; mi < 4; mi++)
#pragma unroll
        for (int ni = 0; ni < 4; ni++)
#pragma unroll
            for (int r = 0; r < 4; r++) c[mi][ni][r] = 0;

    const int wm = (wid >> 2) * 64;
    const int wn = (wid & 3) * 32;
    const int lrow = lane & 15;
    const int lkh  = lane >> 4;

    issue(0, 0);
    issue(1, 1);

#pragma unroll 1
    for (int kc = 0; kc < 4; kc++) {
        const int stg = kc % 3;
        if (kc == 3) { CP_WAIT(0); } else { CP_WAIT(1); }
        __syncthreads();
        if (kc + 2 < 4) issue(kc + 2, (kc + 2) % 3);

        const uint32_t ab = sb + STG_A(stg);
        const uint32_t bb = sb + STG_B(stg);
#pragma unroll
        for (int ks = 0; ks < 4; ks++) {      // 4 x k32 within the 128B chunk
            uint32_t a[4][4];
#pragma unroll
            for (int mi = 0; mi < 4; mi++) {
                uint32_t addr = ab + sw128((uint32_t)((wm + mi * 16 + lrow) * 128 + ks * 32 + lkh * 16));
                LDMATRIX_X4(a[mi][0], a[mi][1], a[mi][2], a[mi][3], addr);
            }
            uint32_t b[4][2];
#pragma unroll
            for (int nj = 0; nj < 2; nj++) {
                uint32_t r0, r1, r2, r3;
                uint32_t addr = bb + sw128((uint32_t)((wn + nj * 16 + lrow) * 128 + ks * 32 + lkh * 16));
                LDMATRIX_X4(r0, r1, r2, r3, addr);
                b[2 * nj][0] = r0; b[2 * nj + 1][0] = r1;
                b[2 * nj][1] = r2; b[2 * nj + 1][1] = r3;
            }
#pragma unroll
            for (int mi = 0; mi < 4; mi++)
#pragma unroll
                for (int ni = 0; ni < 4; ni++)
                    MMA_S8(c[mi][ni], a[mi], b[ni]);
        }
        __syncthreads();
    }

    // ---- stage C tile as u16 keys (128 rows x 256B) ----
    const int crow = lane >> 2;
    const int ccol2 = (lane & 3) * 2;
#pragma unroll
    for (int mi = 0; mi < 4; mi++)
#pragma unroll
        for (int ni = 0; ni < 4; ni++) {
            int m = wm + mi * 16 + crow;
            int n = wn + ni * 8 + ccol2;
            ushort2 lo, hi;
            lo.x = s32_key(c[mi][ni][0]); lo.y = s32_key(c[mi][ni][1]);
            hi.x = s32_key(c[mi][ni][2]); hi.y = s32_key(c[mi][ni][3]);
            *(ushort2*)(smem + m * 256 + n * 2)       = lo;
            *(ushort2*)(smem + (m + 8) * 256 + n * 2) = hi;
        }
    __syncthreads();

    // ---- fused selection: 2 threads per query row, 64 cols each, top-4 ----
    {
        const int row  = tid >> 1;
        const int half = tid & 1;
        int v0 = -1, v1 = -1, v2 = -1, v3 = -1;
        int i0 = 0, i1 = 0, i2 = 0, i3 = 0;
        const int rot = 2 * (row & 15) + half;
#pragma unroll
        for (int p = 0; p < 32; p++) {
            int pp = (p + rot) & 31;
            uint32_t w = *(uint32_t*)(smem + row * 256 + half * 128 + pp * 4);
            int n0 = half * 64 + pp * 2;
#pragma unroll
            for (int h = 0; h < 2; h++) {
                int x = h ? (int)(w >> 16) : (int)(w & 0xFFFFu);
                int n = n0 + h;
                bool p0c = x > v0, p1c = x > v1, p2c = x > v2, p3c = x > v3;
                v3 = p2c ? v2 : (p3c ? x : v3);  i3 = p2c ? i2 : (p3c ? n : i3);
                v2 = p1c ? v1 : (p2c ? x : v2);  i2 = p1c ? i1 : (p2c ? n : i2);
                v1 = p0c ? v0 : (p1c ? x : v1);  i1 = p0c ? i0 : (p1c ? n : i1);
                v0 = p0c ? x  : v0;              i0 = p0c ? n : i0;
            }
        }
        size_t base = ((size_t)(q0 + row) * NTILES + blockIdx.y) * PPT + half * 4;
        ushort4 ks;
        ks.x = (unsigned short)v0; ks.y = (unsigned short)v1;
        ks.z = (unsigned short)v2; ks.w = (unsigned short)v3;
        *(ushort4*)(g_pk + base) = ks;
        *(uchar4*)(g_pl + base) = make_uchar4((unsigned char)i0, (unsigned char)i1,
                                              (unsigned char)i2, (unsigned char)i3);
    }
}

// ---------------------------------------------------------------------------
// Kernel 4: per-query top-48 from packed partials.
// Scan keeps ">"-only compares (ascending-gidx visit order preserves
// lowest-index-on-tie); tournament keeps the cross-lane idx tie-break.
// ---------------------------------------------------------------------------
#define TL 8
__global__ __launch_bounds__(256) void cand_kernel() {
    const int q = blockIdx.x;
    const int tid = threadIdx.x;
    const unsigned short* pk = g_pk + (size_t)q * NTILES * PPT;
    const unsigned char*  pl = g_pl + (size_t)q * NTILES * PPT;

    int tv[TL]; int ti[TL];
#pragma unroll
    for (int i = 0; i < TL; i++) { tv[i] = -1; ti[i] = 0x7fffffff; }

#pragma unroll
    for (int b = 0; b < 4; b++) {
        const int tile = tid * 4 + b;
        uint4 kv = *(const uint4*)(pk + tile * 8);
        uint2 lv = *(const uint2*)(pl + tile * 8);
        uint32_t kw[4] = {kv.x, kv.y, kv.z, kv.w};
        uint32_t lw[2] = {lv.x, lv.y};
#pragma unroll
        for (int e = 0; e < 8; e++) {
            int kk = (int)((kw[e >> 1] >> ((e & 1) * 16)) & 0xFFFFu);
            int gg = tile * 128 + (int)((lw[e >> 2] >> ((e & 3) * 8)) & 0xFFu);
            bool c0 = kk > tv[0], c1 = kk > tv[1], c2 = kk > tv[2], c3 = kk > tv[3];
            bool c4 = kk > tv[4], c5 = kk > tv[5], c6 = kk > tv[6], c7 = kk > tv[7];
            tv[7] = c6 ? tv[6] : (c7 ? kk : tv[7]);  ti[7] = c6 ? ti[6] : (c7 ? gg : ti[7]);
            tv[6] = c5 ? tv[5] : (c6 ? kk : tv[6]);  ti[6] = c5 ? ti[5] : (c6 ? gg : ti[6]);
            tv[5] = c4 ? tv[4] : (c5 ? kk : tv[5]);  ti[5] = c4 ? ti[4] : (c5 ? gg : ti[5]);
            tv[4] = c3 ? tv[3] : (c4 ? kk : tv[4]);  ti[4] = c3 ? ti[3] : (c4 ? gg : ti[4]);
            tv[3] = c2 ? tv[2] : (c3 ? kk : tv[3]);  ti[3] = c2 ? ti[2] : (c3 ? gg : ti[3]);
            tv[2] = c1 ? tv[1] : (c2 ? kk : tv[2]);  ti[2] = c1 ? ti[1] : (c2 ? gg : ti[2]);
            tv[1] = c0 ? tv[0] : (c1 ? kk : tv[1]);  ti[1] = c0 ? ti[0] : (c1 ? gg : ti[1]);
            tv[0] = c0 ? kk : tv[0];                 ti[0] = c0 ? gg : ti[0];
        }
    }

    __shared__ int sv[256 * TL];
    __shared__ int si[256 * TL];
#pragma unroll
    for (int i = 0; i < TL; i++) {
        sv[tid * TL + i] = tv[i];
        si[tid * TL + i] = ti[i];
    }
    __syncthreads();

    if (tid < 32) {
        const int l = tid;
        int hv[8]; int hx[8]; int hp[8];
#pragma unroll
        for (int s = 0; s < 8; s++) {
            int t = l * 8 + s;
            hv[s] = sv[t * TL]; hx[s] = si[t * TL]; hp[s] = 0;
        }
#pragma unroll 1
        for (int sel = 0; sel < NCAND; sel++) {
            int bv = -1; int bi = 0x7fffffff; int bs = 0;
#pragma unroll
            for (int s = 0; s < 8; s++)
                if (hv[s] > bv || (hv[s] == bv && hx[s] < bi)) { bv = hv[s]; bi = hx[s]; bs = s; }
            int wv = bv; int wi = bi; int wl = l;
#pragma unroll
            for (int off = 16; off > 0; off >>= 1) {
                int ov = __shfl_xor_sync(0xffffffffu, wv, off);
                int oi = __shfl_xor_sync(0xffffffffu, wi, off);
                int ol = __shfl_xor_sync(0xffffffffu, wl, off);
                if (ov > wv || (ov == wv && oi < wi)) { wv = ov; wi = oi; wl = ol; }
            }
            if (l == wl) {
                g_cand[q * NCAND + sel] = wi;
                int t = l * 8 + bs;
                hp[bs]++;
                if (hp[bs] < TL) { hv[bs] = sv[t * TL + hp[bs]]; hx[bs] = si[t * TL + hp[bs]]; }
                else             { hv[bs] = -1;                 hx[bs] = 0x7fffffff; }
            }
        }
    }
}

// ---------------------------------------------------------------------------
// Kernel 5: sequential-fp32 rescore of 48 candidates, top-16, write outputs
// ---------------------------------------------------------------------------
#define CHUNK 128
#define CPITCH 129

__global__ __launch_bounds__(256) void refine_kernel(const float* __restrict__ label,
                                                     float* __restrict__ out_scores,
                                                     float* __restrict__ out_idx_f,
                                                     float* __restrict__ out_seqs,
                                                     float* __restrict__ out_labels) {
    const int q = blockIdx.x;
    const int tid = threadIdx.x;

    __shared__ float qn_s[DD];
    __shared__ float chunk[NCAND * CPITCH];
    __shared__ float cv[NCAND];
    __shared__ int   ci[NCAND];
    __shared__ int   sel_idx[KK];

    if (tid < NCAND) ci[tid] = g_cand[q * NCAND + tid];
    for (int d = tid; d < DD; d += 256) qn_s[d] = g_qn[(size_t)q * DD + d];
    __syncthreads();

    float acc = 0.f;
#pragma unroll 1
    for (int ch = 0; ch < DD / CHUNK; ch++) {
        for (int idx = tid; idx < NCAND * CHUNK; idx += 256) {
            int c = idx >> 7, d = idx & (CHUNK - 1);
            chunk[c * CPITCH + d] = g_wt[(size_t)ci[c] * DD + ch * CHUNK + d];
        }
        __syncthreads();
        if (tid < NCAND) {
#pragma unroll
            for (int d = 0; d < CHUNK; d++)
                acc = fmaf(chunk[tid * CPITCH + d], qn_s[ch * CHUNK + d], acc);
        }
        __syncthreads();
    }
    if (tid < NCAND) cv[tid] = acc;
    __syncthreads();

    if (tid == 0) {
        bool used[NCAND] = {};
        for (int r = 0; r < KK; r++) {
            float best = -CUDART_INF_F; int bj = -1; int bidx = 0x7fffffff;
            for (int j = 0; j < NCAND; j++) {
                if (used[j]) continue;
                if (cv[j] > best || (cv[j] == best && ci[j] < bidx)) {
                    best = cv[j]; bj = j; bidx = ci[j];
                }
            }
            used[bj] = true;
            sel_idx[r] = ci[bj];
            out_scores[q * KK + r] = best;
            out_idx_f [q * KK + r] = (float)ci[bj];
            out_labels[q * KK + r] = label[ci[bj]];
        }
    }
    __syncthreads();

#pragma unroll 1
    for (int r = 0; r < KK; r++) {
        const float* row = g_wt + (size_t)sel_idx[r] * DD;
        float* dst = out_seqs + ((size_t)q * KK + r) * DD;
        for (int d = tid; d < DD; d += 256) dst[d] = row[d];
    }
}

// ---------------------------------------------------------------------------
// Launcher
// ---------------------------------------------------------------------------
extern "C" void kernel_launch(void* const* d_in, const int* in_sizes, int n_in,
                              void* d_out, int out_size) {
    const float* queries = (const float*)d_in[0];
    const float* weight  = (const float*)d_in[1];
    const float* label   = (const float*)d_in[2];

    float* out = (float*)d_out;
    float* out_scores = out;
    float* out_idx_f  = out + BQ * KK;
    float* out_seqs   = out + 2 * BQ * KK;
    float* out_labels = out + 2 * BQ * KK + (size_t)BQ * KK * DD;

    cudaFuncSetAttribute(gemm_kernel, cudaFuncAttributeMaxDynamicSharedMemorySize, SMEM_TOTAL);

    normalize_kernel<<<BQ, 128>>>(queries);
    transpose_kernel<<<dim3(NN / 64, DD / 64), 256>>>(weight);
    gemm_kernel<<<dim3(BQ / 128, NN / 128), 256, SMEM_TOTAL>>>();
    cand_kernel<<<BQ, 256>>>();
    refine_kernel<<<BQ, 256>>>(label, out_scores, out_idx_f, out_seqs, out_labels);
}

// round 12
// speedup vs baseline: 1.7847x; 1.6606x over previous
#include <cuda_runtime.h>
#include <cuda_bf16.h>
#include <math_constants.h>
#include <cstdint>

// Problem constants
#define BQ 1024
#define DD 512
#define NN 131072
#define KK 16
#define NCAND 32
#define NTILES (NN / 128)       // 1024 n-tiles
#define PPT 8                   // partial entries per (query, tile)

// ---------------------------------------------------------------------------
// Helpers
// ---------------------------------------------------------------------------
__device__ __forceinline__ uint32_t smem_u32(const void* p) {
    uint32_t a;
    asm("{ .reg .u64 t; cvta.to.shared.u64 t, %1; cvt.u32.u64 %0, t; }" : "=r"(a) : "l"(p));
    return a;
}
__device__ __forceinline__ uint32_t sw128(uint32_t o) { return o ^ ((o >> 3) & 0x70); }

#define CP_ASYNC16(smem_addr, gptr) \
    asm volatile("cp.async.cg.shared.global [%0], [%1], 16;" :: "r"(smem_addr), "l"(gptr))
#define CP_COMMIT() asm volatile("cp.async.commit_group;")
#define CP_WAIT(N)  asm volatile("cp.async.wait_group %0;" :: "n"(N))

#define LDMATRIX_X4(r0, r1, r2, r3, addr) \
    asm volatile("ldmatrix.sync.aligned.m8n8.x4.shared.b16 {%0,%1,%2,%3}, [%4];" \
        : "=r"(r0), "=r"(r1), "=r"(r2), "=r"(r3) : "r"(addr))

#define MMA_BF16(c, a, b) \
    asm volatile("mma.sync.aligned.m16n8k16.row.col.f32.bf16.bf16.f32 " \
        "{%0,%1,%2,%3}, {%4,%5,%6,%7}, {%8,%9}, {%0,%1,%2,%3};" \
        : "+f"((c)[0]), "+f"((c)[1]), "+f"((c)[2]), "+f"((c)[3]) \
        : "r"((a)[0]), "r"((a)[1]), "r"((a)[2]), "r"((a)[3]), "r"((b)[0]), "r"((b)[1]))

// ---------------------------------------------------------------------------
// Scratch
// ---------------------------------------------------------------------------
__device__ float          g_qn[BQ * DD];
__device__ __nv_bfloat16  g_qnb[BQ * DD];
__device__ float          g_wt[(size_t)NN * DD];
__device__ __nv_bfloat16  g_wtb[(size_t)NN * DD];
__device__ float          g_pv[(size_t)BQ * NTILES * PPT];
__device__ int            g_pi[(size_t)BQ * NTILES * PPT];
__device__ int            g_cand[BQ * NCAND];

// ---------------------------------------------------------------------------
// Kernel 1: normalize queries -> fp32 + bf16
// ---------------------------------------------------------------------------
__global__ __launch_bounds__(128) void normalize_kernel(const float* __restrict__ q) {
    int row = blockIdx.x;
    const float* src = q + (size_t)row * DD;
    float v[4];
    float s = 0.f;
#pragma unroll
    for (int i = 0; i < 4; i++) { v[i] = src[threadIdx.x + i * 128]; s += v[i] * v[i]; }
#pragma unroll
    for (int o = 16; o > 0; o >>= 1) s += __shfl_xor_sync(0xffffffffu, s, o);
    __shared__ float red[4];
    if ((threadIdx.x & 31) == 0) red[threadIdx.x >> 5] = s;
    __syncthreads();
    float inv = rsqrtf(red[0] + red[1] + red[2] + red[3]);
#pragma unroll
    for (int i = 0; i < 4; i++) {
        float f = v[i] * inv;
        int d = threadIdx.x + i * 128;
        g_qn[(size_t)row * DD + d]  = f;
        g_qnb[(size_t)row * DD + d] = __float2bfloat16(f);
    }
}

// ---------------------------------------------------------------------------
// Kernel 2: transpose W[D,N] -> W_t[N,D] (float4 gmem reads/writes)
// ---------------------------------------------------------------------------
#define TP 65   // smem pitch (floats)

__global__ __launch_bounds__(256) void transpose_kernel(const float* __restrict__ W) {
    __shared__ float tile[64 * TP];
    const int bx = blockIdx.x;
    const int by = blockIdx.y;
    const int t  = threadIdx.x;

    {
        const int r = t >> 2, s = t & 3;
        const float* src = W + (size_t)(by * 64 + r) * NN + bx * 64 + s * 16;
#pragma unroll
        for (int j = 0; j < 4; j++) {
            float4 v = *(const float4*)(src + j * 4);
            float* dst = &tile[r * TP + s * 16 + j * 4];
            dst[0] = v.x; dst[1] = v.y; dst[2] = v.z; dst[3] = v.w;
        }
    }
    __syncthreads();

    {
        const int nr = t >> 2, s = t & 3;
        const int n = bx * 64 + nr;
        const int d0 = by * 64 + s * 16;
        float vals[16];
#pragma unroll
        for (int j = 0; j < 16; j++)
            vals[j] = tile[(s * 16 + j) * TP + nr];

        float* dst32 = g_wt + (size_t)n * DD + d0;
#pragma unroll
        for (int j = 0; j < 4; j++)
            *(float4*)(dst32 + j * 4) = make_float4(vals[4*j], vals[4*j+1], vals[4*j+2], vals[4*j+3]);

        uint32_t pk[8];
#pragma unroll
        for (int j = 0; j < 8; j++) {
            __nv_bfloat162 b2 = __float22bfloat162_rn(make_float2(vals[2*j], vals[2*j+1]));
            pk[j] = *(uint32_t*)&b2;
        }
        uint4* dst16 = (uint4*)(g_wtb + (size_t)n * DD + d0);
        dst16[0] = make_uint4(pk[0], pk[1], pk[2], pk[3]);
        dst16[1] = make_uint4(pk[4], pk[5], pk[6], pk[7]);
    }
}

// ---------------------------------------------------------------------------
// Kernel 3: bf16 HMMA GEMM, 4 warps x 64x64 warp tiles (high ILP variant).
// CTA tile 128x128, BK=64, 128 threads, 3-stage cp.async pipeline.
// Per ks-step per warp: 8 LDSM.x4 + 32 independent MMAs (MMA:LDSM = 4).
// Fused per-(row, half-tile) top-4 selection epilogue (round-6 semantics).
// ---------------------------------------------------------------------------
#define BKG 64
#define STG_BYTES 16384
#define AOFFS(s) ((uint32_t)((s) * STG_BYTES))
#define BOFFS(s) ((uint32_t)(49152 + (s) * STG_BYTES))
#define SMEM_TOTAL 98304

__global__ __launch_bounds__(128, 2) void gemm_kernel() {
    extern __shared__ char smem[];
    const uint32_t sb = smem_u32(smem);
    const int tid = threadIdx.x, wid = tid >> 5, lane = tid & 31;
    const int q0 = blockIdx.x * 128;
    const int nb = blockIdx.y * 128;

    const int ldrow = tid >> 3;          // base row 0..15 (x8 -> 128 rows)
    const int ldseg = tid & 7;           // 16B segment within 128B row

    auto issue = [&](int kc, int stg) {
        const __nv_bfloat16* As = g_qnb + (size_t)q0 * DD + kc * BKG;
        const __nv_bfloat16* Bs = g_wtb + (size_t)nb * DD + kc * BKG;
#pragma unroll
        for (int i = 0; i < 8; i++) {
            int row = ldrow + i * 16;
            uint32_t off = sw128((uint32_t)(row * 128 + ldseg * 16));
            CP_ASYNC16(sb + AOFFS(stg) + off, As + (size_t)row * DD + ldseg * 8);
            CP_ASYNC16(sb + BOFFS(stg) + off, Bs + (size_t)row * DD + ldseg * 8);
        }
        CP_COMMIT();
    };

    float c[4][8][4];
#pragma unroll
    for (int mi = 0; mi < 4; mi++)
#pragma unroll
        for (int ni = 0; ni < 8; ni++)
#pragma unroll
            for (int r = 0; r < 4; r++) c[mi][ni][r] = 0.f;

    const int wm = (wid >> 1) * 64;      // warp m origin (0 / 64)
    const int wn = (wid & 1) * 64;       // warp n origin (0 / 64)
    const int lrow = lane & 15;
    const int lkh  = lane >> 4;

    issue(0, 0);
    issue(1, 1);

#pragma unroll 1
    for (int kc = 0; kc < 8; kc++) {
        const int stg = kc % 3;
        if (kc == 7) { CP_WAIT(0); } else { CP_WAIT(1); }
        __syncthreads();
        if (kc + 2 < 8) issue(kc + 2, (kc + 2) % 3);

        const uint32_t ab = sb + AOFFS(stg);
        const uint32_t bb = sb + BOFFS(stg);
#pragma unroll
        for (int ks = 0; ks < 4; ks++) {
            const int k0 = ks * 16;
            uint32_t a[4][4];
#pragma unroll
            for (int mi = 0; mi < 4; mi++) {
                uint32_t addr = ab + sw128((uint32_t)((wm + mi * 16 + lrow) * 128 + (k0 + lkh * 8) * 2));
                LDMATRIX_X4(a[mi][0], a[mi][1], a[mi][2], a[mi][3], addr);
            }
            uint32_t b[8][2];
#pragma unroll
            for (int nj = 0; nj < 4; nj++) {
                uint32_t r0, r1, r2, r3;
                uint32_t addr = bb + sw128((uint32_t)((wn + nj * 16 + lrow) * 128 + (k0 + lkh * 8) * 2));
                LDMATRIX_X4(r0, r1, r2, r3, addr);
                b[2 * nj][0] = r0; b[2 * nj + 1][0] = r1;
                b[2 * nj][1] = r2; b[2 * nj + 1][1] = r3;
            }
#pragma unroll
            for (int mi = 0; mi < 4; mi++)
#pragma unroll
                for (int ni = 0; ni < 8; ni++)
                    MMA_BF16(c[mi][ni], a[mi], b[ni]);
        }
        __syncthreads();
    }

    // ---- stage C tile (128x128 bf16) in smem (reuses stage SMEM) ----
    const int crow = lane >> 2;
    const int ccol2 = (lane & 3) * 2;
#pragma unroll
    for (int mi = 0; mi < 4; mi++)
#pragma unroll
        for (int ni = 0; ni < 8; ni++) {
            int m = wm + mi * 16 + crow;
            int n = wn + ni * 8 + ccol2;
            __nv_bfloat162 p0 = __float22bfloat162_rn(make_float2(c[mi][ni][0], c[mi][ni][1]));
            __nv_bfloat162 p1 = __float22bfloat162_rn(make_float2(c[mi][ni][2], c[mi][ni][3]));
            *(__nv_bfloat162*)(smem + m * 256 + n * 2)       = p0;
            *(__nv_bfloat162*)(smem + (m + 8) * 256 + n * 2) = p1;
        }
    __syncthreads();

    // ---- fused selection: 1 thread per query row, two 64-col halves ----
    {
        const int row = tid;             // 0..127
        const int rot = row & 31;        // conflict-free: lanes hit distinct banks
#pragma unroll
        for (int half = 0; half < 2; half++) {
            float v0 = -CUDART_INF_F, v1 = -CUDART_INF_F, v2 = -CUDART_INF_F, v3 = -CUDART_INF_F;
            int   i0 = 0x7fffffff, i1 = 0x7fffffff, i2 = 0x7fffffff, i3 = 0x7fffffff;
#pragma unroll
            for (int p = 0; p < 32; p++) {
                int pp = (p + rot) & 31;
                uint32_t w = *(uint32_t*)(smem + row * 256 + half * 128 + pp * 4);
                __nv_bfloat162 b2 = *(__nv_bfloat162*)&w;
                float x0 = __low2float(b2);
                float x1 = __high2float(b2);
                int   n0 = nb + half * 64 + pp * 2;
#pragma unroll
                for (int h = 0; h < 2; h++) {
                    float x = h ? x1 : x0;
                    int   n = n0 + h;
                    bool p0c = x > v0, p1c = x > v1, p2c = x > v2, p3c = x > v3;
                    v3 = p2c ? v2 : (p3c ? x : v3);  i3 = p2c ? i2 : (p3c ? n : i3);
                    v2 = p1c ? v1 : (p2c ? x : v2);  i2 = p1c ? i1 : (p2c ? n : i2);
                    v1 = p0c ? v0 : (p1c ? x : v1);  i1 = p0c ? i0 : (p1c ? n : i1);
                    v0 = p0c ? x  : v0;              i0 = p0c ? n : i0;
                }
            }
            size_t base = ((size_t)(q0 + row) * NTILES + blockIdx.y) * PPT + half * 4;
            *(float4*)(g_pv + base) = make_float4(v0, v1, v2, v3);
            *(int4*)  (g_pi + base) = make_int4(i0, i1, i2, i3);
        }
    }
}

// ---------------------------------------------------------------------------
// Kernel 4: per-query top-32 from the 8192 partials (round-6 version)
// ---------------------------------------------------------------------------
#define TL 8
__global__ __launch_bounds__(256) void cand_kernel() {
    const int q = blockIdx.x;
    const int tid = threadIdx.x;
    const float* pv = g_pv + (size_t)q * NTILES * PPT;
    const int*   pi = g_pi + (size_t)q * NTILES * PPT;

    float tv[TL]; int ti[TL];
#pragma unroll
    for (int i = 0; i < TL; i++) { tv[i] = -CUDART_INF_F; ti[i] = 0x7fffffff; }

#pragma unroll
    for (int b = 0; b < 8; b++) {
        float4 v = *(const float4*)(pv + tid * 32 + b * 4);
        int4   x = *(const int4*)(pi + tid * 32 + b * 4);
        float xs[4] = {v.x, v.y, v.z, v.w};
        int   ns[4] = {x.x, x.y, x.z, x.w};
#pragma unroll
        for (int e = 0; e < 4; e++) {
            float xx = xs[e]; int nn = ns[e];
            bool c0 = xx > tv[0], c1 = xx > tv[1], c2 = xx > tv[2], c3 = xx > tv[3];
            bool c4 = xx > tv[4], c5 = xx > tv[5], c6 = xx > tv[6], c7 = xx > tv[7];
            tv[7] = c6 ? tv[6] : (c7 ? xx : tv[7]);  ti[7] = c6 ? ti[6] : (c7 ? nn : ti[7]);
            tv[6] = c5 ? tv[5] : (c6 ? xx : tv[6]);  ti[6] = c5 ? ti[5] : (c6 ? nn : ti[6]);
            tv[5] = c4 ? tv[4] : (c5 ? xx : tv[5]);  ti[5] = c4 ? ti[4] : (c5 ? nn : ti[5]);
            tv[4] = c3 ? tv[3] : (c4 ? xx : tv[4]);  ti[4] = c3 ? ti[3] : (c4 ? nn : ti[4]);
            tv[3] = c2 ? tv[2] : (c3 ? xx : tv[3]);  ti[3] = c2 ? ti[2] : (c3 ? nn : ti[3]);
            tv[2] = c1 ? tv[1] : (c2 ? xx : tv[2]);  ti[2] = c1 ? ti[1] : (c2 ? nn : ti[2]);
            tv[1] = c0 ? tv[0] : (c1 ? xx : tv[1]);  ti[1] = c0 ? ti[0] : (c1 ? nn : ti[1]);
            tv[0] = c0 ? xx : tv[0];                 ti[0] = c0 ? nn : ti[0];
        }
    }

    __shared__ float sv[256 * TL];
    __shared__ int   si[256 * TL];
#pragma unroll
    for (int i = 0; i < TL; i++) {
        sv[tid * TL + i] = tv[i];
        si[tid * TL + i] = ti[i];
    }
    __syncthreads();

    if (tid < 32) {
        const int l = tid;
        float hv[8]; int hx[8]; int hp[8];
#pragma unroll
        for (int s = 0; s < 8; s++) {
            int t = l * 8 + s;
            hv[s] = sv[t * TL]; hx[s] = si[t * TL]; hp[s] = 0;
        }
#pragma unroll 1
        for (int sel = 0; sel < NCAND; sel++) {
            float bv = -CUDART_INF_F; int bi = 0x7fffffff; int bs = 0;
#pragma unroll
            for (int s = 0; s < 8; s++)
                if (hv[s] > bv || (hv[s] == bv && hx[s] < bi)) { bv = hv[s]; bi = hx[s]; bs = s; }
            float wv = bv; int wi = bi; int wl = l;
#pragma unroll
            for (int off = 16; off > 0; off >>= 1) {
                float ov = __shfl_xor_sync(0xffffffffu, wv, off);
                int   oi = __shfl_xor_sync(0xffffffffu, wi, off);
                int   ol = __shfl_xor_sync(0xffffffffu, wl, off);
                if (ov > wv || (ov == wv && oi < wi)) { wv = ov; wi = oi; wl = ol; }
            }
            if (l == wl) {
                g_cand[q * NCAND + sel] = wi;
                int t = l * 8 + bs;
                hp[bs]++;
                if (hp[bs] < TL) { hv[bs] = sv[t * TL + hp[bs]]; hx[bs] = si[t * TL + hp[bs]]; }
                else             { hv[bs] = -CUDART_INF_F;      hx[bs] = 0x7fffffff; }
            }
        }
    }
}

// ---------------------------------------------------------------------------
// Kernel 5: sequential-fp32 rescore of 32 candidates, top-16, write outputs
// ---------------------------------------------------------------------------
#define CHUNK 128
#define CPITCH 129

__global__ __launch_bounds__(256) void refine_kernel(const float* __restrict__ label,
                                                     float* __restrict__ out_scores,
                                                     float* __restrict__ out_idx_f,
                                                     float* __restrict__ out_seqs,
                                                     float* __restrict__ out_labels) {
    const int q = blockIdx.x;
    const int tid = threadIdx.x;

    __shared__ float qn_s[DD];
    __shared__ float chunk[NCAND * CPITCH];
    __shared__ float cv[NCAND];
    __shared__ int   ci[NCAND];
    __shared__ int   sel_idx[KK];

    if (tid < NCAND) ci[tid] = g_cand[q * NCAND + tid];
    for (int d = tid; d < DD; d += 256) qn_s[d] = g_qn[(size_t)q * DD + d];
    __syncthreads();

    float acc = 0.f;
#pragma unroll 1
    for (int ch = 0; ch < DD / CHUNK; ch++) {
        for (int idx = tid; idx < NCAND * CHUNK; idx += 256) {
            int c = idx >> 7, d = idx & (CHUNK - 1);
            chunk[c * CPITCH + d] = g_wt[(size_t)ci[c] * DD + ch * CHUNK + d];
        }
        __syncthreads();
        if (tid < NCAND) {
#pragma unroll
            for (int d = 0; d < CHUNK; d++)
                acc = fmaf(chunk[tid * CPITCH + d], qn_s[ch * CHUNK + d], acc);
        }
        __syncthreads();
    }
    if (tid < NCAND) cv[tid] = acc;
    __syncthreads();

    if (tid == 0) {
        bool used[NCAND] = {};
        for (int r = 0; r < KK; r++) {
            float best = -CUDART_INF_F; int bj = -1; int bidx = 0x7fffffff;
            for (int j = 0; j < NCAND; j++) {
                if (used[j]) continue;
                if (cv[j] > best || (cv[j] == best && ci[j] < bidx)) {
                    best = cv[j]; bj = j; bidx = ci[j];
                }
            }
            used[bj] = true;
            sel_idx[r] = ci[bj];
            out_scores[q * KK + r] = best;
            out_idx_f [q * KK + r] = (float)ci[bj];
            out_labels[q * KK + r] = label[ci[bj]];
        }
    }
    __syncthreads();

#pragma unroll 1
    for (int r = 0; r < KK; r++) {
        const float* row = g_wt + (size_t)sel_idx[r] * DD;
        float* dst = out_seqs + ((size_t)q * KK + r) * DD;
        for (int d = tid; d < DD; d += 256) dst[d] = row[d];
    }
}

// ---------------------------------------------------------------------------
// Launcher
// ---------------------------------------------------------------------------
extern "C" void kernel_launch(void* const* d_in, const int* in_sizes, int n_in,
                              void* d_out, int out_size) {
    const float* queries = (const float*)d_in[0];
    const float* weight  = (const float*)d_in[1];
    const float* label   = (const float*)d_in[2];

    float* out = (float*)d_out;
    float* out_scores = out;
    float* out_idx_f  = out + BQ * KK;
    float* out_seqs   = out + 2 * BQ * KK;
    float* out_labels = out + 2 * BQ * KK + (size_t)BQ * KK * DD;

    cudaFuncSetAttribute(gemm_kernel, cudaFuncAttributeMaxDynamicSharedMemorySize, SMEM_TOTAL);

    normalize_kernel<<<BQ, 128>>>(queries);
    transpose_kernel<<<dim3(NN / 64, DD / 64), 256>>>(weight);
    gemm_kernel<<<dim3(BQ / 128, NN / 128), 128, SMEM_TOTAL>>>();
    cand_kernel<<<BQ, 256>>>();
    refine_kernel<<<BQ, 256>>>(label, out_scores, out_idx_f, out_seqs, out_labels);
}